// round 4
// baseline (speedup 1.0000x reference)
#include <cuda_runtime.h>
#include <cuda_bf16.h>
#include <math.h>

// Problem constants
#define Hh 4
#define Nn 512
#define Dd 64
#define Ee (Nn*Nn)          // 262144 = 2^18
#define HE (Hh*Ee)          // 1048576
#define Kk 64
#define CAND_MAX 16384

#define JAX_PARTITIONABLE 1

// ---------------- scratch (static device globals; no allocation) ----------------
__device__ float g_A[Hh*Nn*Dd];
__device__ float g_B[Hh*Nn*Dd];
__device__ float g_g0[HE];
__device__ float g_g1[HE];
__device__ unsigned g_hist[Hh][2048];   // level-1 histogram (bits>>21)
__device__ unsigned g_hist2[Hh][2048];  // level-2 histogram ((bits>>10)&2047) within b1*
__device__ int g_bstar[Hh];
__device__ int g_cabove[Hh];
__device__ unsigned long long g_cand[Hh][CAND_MAX];
__device__ int g_candn[Hh];

// ---------------- threefry2x32 (JAX-exact) ----------------
__device__ __forceinline__ unsigned rotl32(unsigned x, int r) { return __funnelshift_l(x, x, r); }
__device__ __forceinline__ void tf_round(unsigned &x0, unsigned &x1, int r) {
    x0 += x1; x1 = rotl32(x1, r); x1 ^= x0;
}
__device__ __forceinline__ void threefry2x32(unsigned x0, unsigned x1, unsigned &o0, unsigned &o1) {
    const unsigned k0 = 0u, k1 = 42u;
    const unsigned k2 = k0 ^ k1 ^ 0x1BD11BDAu;
    x0 += k0; x1 += k1;
    tf_round(x0,x1,13); tf_round(x0,x1,15); tf_round(x0,x1,26); tf_round(x0,x1,6);
    x0 += k1; x1 += k2 + 1u;
    tf_round(x0,x1,17); tf_round(x0,x1,29); tf_round(x0,x1,16); tf_round(x0,x1,24);
    x0 += k2; x1 += k0 + 2u;
    tf_round(x0,x1,13); tf_round(x0,x1,15); tf_round(x0,x1,26); tf_round(x0,x1,6);
    x0 += k0; x1 += k1 + 3u;
    tf_round(x0,x1,17); tf_round(x0,x1,29); tf_round(x0,x1,16); tf_round(x0,x1,24);
    x0 += k1; x1 += k2 + 4u;
    tf_round(x0,x1,13); tf_round(x0,x1,15); tf_round(x0,x1,26); tf_round(x0,x1,6);
    x0 += k2; x1 += k0 + 5u;
    o0 = x0; o1 = x1;
}

__device__ __forceinline__ unsigned random_bits_at(unsigned i) {
#if JAX_PARTITIONABLE
    unsigned o0, o1;
    threefry2x32(0u, i, o0, o1);
    return o0 ^ o1;
#else
    const unsigned halfS = (unsigned)(HE);
    unsigned o0, o1;
    if (i < halfS) { threefry2x32(i, i + halfS, o0, o1); return o0; }
    else           { threefry2x32(i - halfS, i, o0, o1); return o1; }
#endif
}

// ---------------- double-float (2x f32) natural log, ~2^-45 relative accuracy ----
__device__ __forceinline__ float log_df(float x) {
    int ib = __float_as_int(x);
    int e  = (ib - 0x3f3504f3) >> 23;
    float m = __int_as_float(ib - (e << 23));
    float f = m - 1.0f;
    float uh = 2.0f + f;
    float ul = f - (uh - 2.0f);
    float r  = 1.0f / uh;
    float sh = f * r;
    float t  = fmaf(-sh, uh, f);
    t = fmaf(-sh, ul, t);
    float sl = t * r;
    float zh = sh * sh;
    float zl = fmaf(sh, sh, -zh) + 2.0f * sh * sl;
    float C = fmaf(zh, 0.18181818183f, 0.22222222222f);
    C = fmaf(zh, C, 0.28571428571f);
    C = fmaf(zh, C, 0.4f);
    C = fmaf(zh, C, 0.66666666667f);
    float p    = sh * zh;
    float tail = fmaf(p, C, 2.0f * sl);
    tail = fmaf(sh * zl, 0.66666666667f, tail);
    float lh = 2.0f * sh;
    float fe = (float)e;
    float A  = fe * 0.69314575195f;
    float rh = A + lh;
    float rl = lh - (rh - A);
    float small = fmaf(fe, 1.4286067653e-06f, tail) + rl;
    return rh + small;
}

__device__ __forceinline__ float gumbel_from_bits(unsigned bits) {
    float U  = __uint_as_float((bits >> 9) | 0x3f800000u) - 1.0f;
    float t1 = U + 1e-10f;
    float L1 = log_df(t1);
    float t2 = (0.0f - L1) + 1e-10f;
    float L2 = log_df(t2);
    return 0.0f - L2;
}

// ---------------- fused prep: node transform + gumbel noise ----------------
// blocks [0,1024): node rows (2 per block).  blocks [1024,5120): gumbel.
__global__ __launch_bounds__(256) void prep_kernel(const float* __restrict__ feats,
                                                   const float* __restrict__ Wout,
                                                   const float* __restrict__ bout) {
    int b = blockIdx.x;
    if (b < 1024) {
        __shared__ float f[2][Dd];
        int half = threadIdx.x >> 7;       // 0/1: which row of the pair
        int t    = threadIdx.x & 127;
        int row  = b * 2 + half;
        if (t < Dd) f[half][t] = feats[row * Dd + t];
        __syncthreads();
        int col  = t & 63;
        bool isA = (t < 64);
        const float* W = Wout + (isA ? 0 : Dd * Dd);
        float acc = isA ? bout[col] : 0.0f;
#pragma unroll
        for (int k = 0; k < Dd; k++) acc = fmaf(f[half][k], W[k * Dd + col], acc);
        if (isA) g_A[row * Dd + col] = acc;
        else     g_B[row * Dd + col] = acc;
    } else {
        int j = (b - 1024) * 256 + threadIdx.x;   // 0..HE-1
        unsigned i0 = 2u * (unsigned)j;
        g_g0[j] = gumbel_from_bits(random_bits_at(i0));
        g_g1[j] = gumbel_from_bits(random_bits_at(i0 + 1u));
    }
}

// ---------------- edge kernel: 32x32 (snd x rec) tile, 4 edges/thread -------
// grid (16,16,4) = 1024 blocks, 256 threads.
__global__ __launch_bounds__(256) void edge_kernel(const float* __restrict__ Wcat,
                                                   const float* __restrict__ bcat,
                                                   float* __restrict__ out) {
    int st = blockIdx.x, rt = blockIdx.y, head = blockIdx.z;
    __shared__ float As[64][34];    // [k][snd], even row stride -> 8B-aligned float2
    __shared__ float Bs[64][34];    // [k][rec]
    __shared__ float wc0[64], wc1[64];
    __shared__ unsigned hist[2048];
    int t = threadIdx.x;
    for (int i = t; i < 2048; i += 256) hist[i] = 0u;
    if (t < 64) { wc0[t] = Wcat[t * 2]; wc1[t] = Wcat[t * 2 + 1]; }

    // load 32x64 slabs of A and B, transposed into [k][node] layout
    const float4* A4 = (const float4*)(g_A + (head * Nn + st * 32) * Dd);
    const float4* B4 = (const float4*)(g_B + (head * Nn + rt * 32) * Dd);
#pragma unroll
    for (int q = 0; q < 2; q++) {
        int i4 = t * 2 + q;                 // 0..511 float4s
        int s  = i4 >> 4;                   // node 0..31
        int kb = (i4 & 15) * 4;             // k base
        float4 va = A4[i4];
        float4 vb = B4[i4];
        As[kb + 0][s] = va.x; As[kb + 1][s] = va.y; As[kb + 2][s] = va.z; As[kb + 3][s] = va.w;
        Bs[kb + 0][s] = vb.x; Bs[kb + 1][s] = vb.y; Bs[kb + 2][s] = vb.z; Bs[kb + 3][s] = vb.w;
    }
    __syncthreads();

    int tx = t & 15, ty = t >> 4;          // snd pair tx*2, rec pair ty*2
    float acc0[2][2], acc1[2][2];
#pragma unroll
    for (int i = 0; i < 2; i++)
#pragma unroll
        for (int j = 0; j < 2; j++) { acc0[i][j] = 0.f; acc1[i][j] = 0.f; }

#pragma unroll 8
    for (int k = 0; k < 64; k++) {
        float2 a = *(const float2*)&As[k][tx * 2];
        float2 b = *(const float2*)&Bs[k][ty * 2];
        float w0 = wc0[k], w1 = wc1[k];
        float av[2] = {a.x, a.y};
        float bv[2] = {b.x, b.y};
#pragma unroll
        for (int i = 0; i < 2; i++)
#pragma unroll
            for (int j = 0; j < 2; j++) {
                float hr = fmaxf(av[j] + bv[i], 0.0f);
                acc0[i][j] = fmaf(hr, w0, acc0[i][j]);
                acc1[i][j] = fmaf(hr, w1, acc1[i][j]);
            }
    }

    float bc0 = bcat[0], bc1 = bcat[1];
    int rec0 = rt * 32 + ty * 2;
    int snd0 = st * 32 + tx * 2;
#pragma unroll
    for (int i = 0; i < 2; i++) {
        int gidx = head * Ee + (rec0 + i) * Nn + snd0;   // even -> 8B aligned
        float2 G0 = *reinterpret_cast<const float2*>(g_g0 + gidx);
        float2 G1 = *reinterpret_cast<const float2*>(g_g1 + gidx);
        float g0a[2] = {G0.x, G0.y};
        float g1a[2] = {G1.x, G1.y};
        float cma[2], pa[2];
#pragma unroll
        for (int j = 0; j < 2; j++) {
            float l0 = acc0[i][j] + bc0;
            float l1 = acc1[i][j] + bc1;
            float m  = fmaxf(l0, l1);
            float e0v = expf(l0 - m);
            float e1v = expf(l1 - m);
            float p = e1v / (e0v + e1v);
            pa[j] = p;
            float s0 = l0 + g0a[j];
            float s1 = l1 + g1a[j];
            cma[j] = (s1 > s0) ? 1.0f : 0.0f;
            atomicAdd(&hist[__float_as_uint(p) >> 21], 1u);
        }
        float2 cmv; cmv.x = cma[0]; cmv.y = cma[1];
        float2 pv;  pv.x  = pa[0];  pv.y  = pa[1];
        float2 zv;  zv.x = 0.f; zv.y = 0.f;
        *reinterpret_cast<float2*>(out + gidx)          = cmv;
        *reinterpret_cast<float2*>(out + HE + gidx)     = pv;
        *reinterpret_cast<float2*>(out + 2 * HE + gidx) = zv;
    }
    __syncthreads();
    for (int i = t; i < 2048; i += 256)
        if (hist[i]) atomicAdd(&g_hist[head][i], hist[i]);
}

// ---------------- suffix-scan threshold (generic pointer outputs) -----------
__device__ __forceinline__ void threshold_scan(const unsigned* hist, int target,
                                               int* bstar_out, int* cabove_out) {
    int t = threadIdx.x;
    __shared__ int psum[256];
    int local[8];
    int base = t * 8;
    int ls = 0;
#pragma unroll
    for (int i = 0; i < 8; i++) { local[i] = (int)hist[base + i]; ls += local[i]; }
    psum[t] = ls;
    __syncthreads();
    for (int off = 1; off < 256; off <<= 1) {
        int add = (t + off < 256) ? psum[t + off] : 0;
        __syncthreads();
        psum[t] += add;
        __syncthreads();
    }
    int cum = psum[t] - ls;   // strictly above this chunk
#pragma unroll
    for (int i = 7; i >= 0; i--) {
        if (cum < target && cum + local[i] >= target) {
            *bstar_out = base + i;
            *cabove_out = cum;
        }
        cum += local[i];
    }
    __syncthreads();
}

__global__ __launch_bounds__(256) void threshold1_kernel() {
    int h = blockIdx.x;
    threshold_scan(g_hist[h], Kk, &g_bstar[h], &g_cabove[h]);
    // restore zeros for next graph replay
    int base = threadIdx.x * 8;
#pragma unroll
    for (int i = 0; i < 8; i++) g_hist[h][base + i] = 0u;
}

// Mark bins > b1*; compact bin == b1* into g_cand + build level-2 histogram
__global__ __launch_bounds__(256) void collect1_kernel(float* __restrict__ out) {
    int idx = blockIdx.x * 256 + threadIdx.x;
    if (idx >= HE) return;
    int h = idx >> 18;
    unsigned e = (unsigned)(idx & (Ee - 1));
    unsigned bits = __float_as_uint(out[HE + idx]);
    int bin = (int)(bits >> 21);
    int bs = g_bstar[h];
    if (bin > bs) {
        out[2 * HE + idx] = 1.0f;
    } else if (bin == bs) {
        atomicAdd(&g_hist2[h][(bits >> 10) & 2047], 1u);
        int p = atomicAdd(&g_candn[h], 1);
        if (p < CAND_MAX)
            g_cand[h][p] = (((unsigned long long)bits) << 32)
                         | (unsigned long long)((unsigned)(Ee - 1) - e);
    }
}

// Per head: threshold2 + mark/collect from compacted list + iterative topk
__global__ __launch_bounds__(256) void final_kernel(float* __restrict__ out) {
    int h = blockIdx.x, t = threadIdx.x;
    __shared__ int sb2, sc2;
    threshold_scan(g_hist2[h], Kk - g_cabove[h], &sb2, &sc2);
    {   // restore hist2 zeros
        int base = t * 8;
#pragma unroll
        for (int i = 0; i < 8; i++) g_hist2[h][base + i] = 0u;
    }
    __syncthreads();
    int b2 = sb2, c2 = sc2;

    __shared__ unsigned long long lv[1024];
    __shared__ int lc;
    if (t == 0) lc = 0;
    __syncthreads();
    int n = g_candn[h]; if (n > CAND_MAX) n = CAND_MAX;
    for (int i = t; i < n; i += 256) {
        unsigned long long v = g_cand[h][i];
        unsigned bits = (unsigned)(v >> 32);
        int bin2 = (int)((bits >> 10) & 2047);
        if (bin2 > b2) {
            unsigned e = (unsigned)(Ee - 1) - (unsigned)(v & 0xffffffffull);
            out[2 * HE + h * Ee + (int)e] = 1.0f;
        } else if (bin2 == b2) {
            int p = atomicAdd(&lc, 1);
            if (p < 1024) lv[p] = v;
        }
    }
    __syncthreads();
    int take = Kk - g_cabove[h] - c2;
    int m = lc; if (m > 1024) m = 1024;
    __shared__ unsigned long long wmax[8];
    for (int it = 0; it < take; it++) {
        unsigned long long best = 0ull;
        for (int i = t; i < m; i += 256) { unsigned long long v = lv[i]; if (v > best) best = v; }
#pragma unroll
        for (int o = 16; o > 0; o >>= 1) {
            unsigned long long v = __shfl_xor_sync(0xffffffffu, best, o);
            if (v > best) best = v;
        }
        if ((t & 31) == 0) wmax[t >> 5] = best;
        __syncthreads();
        if (t == 0) {
            unsigned long long w = wmax[0];
#pragma unroll
            for (int i = 1; i < 8; i++) if (wmax[i] > w) w = wmax[i];
            wmax[0] = w;
        }
        __syncthreads();
        unsigned long long win = wmax[0];
        for (int i = t; i < m; i += 256) if (lv[i] == win) lv[i] = 0ull;
        if (t == 0) {
            unsigned e = (unsigned)(Ee - 1) - (unsigned)(win & 0xffffffffull);
            out[2 * HE + h * Ee + (int)e] = 1.0f;
        }
        __syncthreads();
    }
    if (t == 0) g_candn[h] = 0;   // restore for next replay
}

// ---------------- launch ----------------
extern "C" void kernel_launch(void* const* d_in, const int* in_sizes, int n_in,
                              void* d_out, int out_size) {
    const float* feats = (const float*)d_in[0];
    const float* W_out = (const float*)d_in[1];
    const float* b_out = (const float*)d_in[2];
    const float* W_cat = (const float*)d_in[3];
    const float* b_cat = (const float*)d_in[4];
    float* out = (float*)d_out;

    prep_kernel<<<1024 + HE / 256, 256>>>(feats, W_out, b_out);
    {
        dim3 grid(Nn / 32, Nn / 32, Hh);
        edge_kernel<<<grid, 256>>>(W_cat, b_cat, out);
    }
    threshold1_kernel<<<Hh, 256>>>();
    collect1_kernel<<<HE / 256, 256>>>(out);
    final_kernel<<<Hh, 256>>>(out);
}

// round 6
// speedup vs baseline: 1.0734x; 1.0734x over previous
#include <cuda_runtime.h>
#include <cuda_bf16.h>
#include <math.h>

// Problem constants
#define Hh 4
#define Nn 512
#define Dd 64
#define Ee (Nn*Nn)          // 262144 = 2^18
#define HE (Hh*Ee)          // 1048576
#define Kk 64
#define CAND_MAX 16384

#define JAX_PARTITIONABLE 1

// ---------------- scratch (static device globals; no allocation) ----------------
__device__ float g_A[Hh*Nn*Dd];
__device__ float g_B[Hh*Nn*Dd];
__device__ float g_g0[HE];
__device__ float g_g1[HE];
__device__ unsigned g_hist[Hh][2048];   // level-1 histogram (bits>>21)
__device__ unsigned g_hist2[Hh][2048];  // level-2 histogram ((bits>>10)&2047) within b1*
__device__ int g_bstar[Hh];
__device__ int g_cabove[Hh];
__device__ unsigned long long g_cand[Hh][CAND_MAX];
__device__ int g_candn[Hh];

// ---------------- threefry2x32 (JAX-exact) ----------------
__device__ __forceinline__ unsigned rotl32(unsigned x, int r) { return __funnelshift_l(x, x, r); }
__device__ __forceinline__ void tf_round(unsigned &x0, unsigned &x1, int r) {
    x0 += x1; x1 = rotl32(x1, r); x1 ^= x0;
}
__device__ __forceinline__ void threefry2x32(unsigned x0, unsigned x1, unsigned &o0, unsigned &o1) {
    const unsigned k0 = 0u, k1 = 42u;
    const unsigned k2 = k0 ^ k1 ^ 0x1BD11BDAu;
    x0 += k0; x1 += k1;
    tf_round(x0,x1,13); tf_round(x0,x1,15); tf_round(x0,x1,26); tf_round(x0,x1,6);
    x0 += k1; x1 += k2 + 1u;
    tf_round(x0,x1,17); tf_round(x0,x1,29); tf_round(x0,x1,16); tf_round(x0,x1,24);
    x0 += k2; x1 += k0 + 2u;
    tf_round(x0,x1,13); tf_round(x0,x1,15); tf_round(x0,x1,26); tf_round(x0,x1,6);
    x0 += k0; x1 += k1 + 3u;
    tf_round(x0,x1,17); tf_round(x0,x1,29); tf_round(x0,x1,16); tf_round(x0,x1,24);
    x0 += k1; x1 += k2 + 4u;
    tf_round(x0,x1,13); tf_round(x0,x1,15); tf_round(x0,x1,26); tf_round(x0,x1,6);
    x0 += k2; x1 += k0 + 5u;
    o0 = x0; o1 = x1;
}

__device__ __forceinline__ unsigned random_bits_at(unsigned i) {
#if JAX_PARTITIONABLE
    unsigned o0, o1;
    threefry2x32(0u, i, o0, o1);
    return o0 ^ o1;
#else
    const unsigned halfS = (unsigned)(HE);
    unsigned o0, o1;
    if (i < halfS) { threefry2x32(i, i + halfS, o0, o1); return o0; }
    else           { threefry2x32(i - halfS, i, o0, o1); return o1; }
#endif
}

// ---------------- double-float (2x f32) natural log, ~2^-45 relative accuracy ----
__device__ __forceinline__ float log_df(float x) {
    int ib = __float_as_int(x);
    int e  = (ib - 0x3f3504f3) >> 23;
    float m = __int_as_float(ib - (e << 23));
    float f = m - 1.0f;
    float uh = 2.0f + f;
    float ul = f - (uh - 2.0f);
    float r  = 1.0f / uh;
    float sh = f * r;
    float t  = fmaf(-sh, uh, f);
    t = fmaf(-sh, ul, t);
    float sl = t * r;
    float zh = sh * sh;
    float zl = fmaf(sh, sh, -zh) + 2.0f * sh * sl;
    float C = fmaf(zh, 0.18181818183f, 0.22222222222f);
    C = fmaf(zh, C, 0.28571428571f);
    C = fmaf(zh, C, 0.4f);
    C = fmaf(zh, C, 0.66666666667f);
    float p    = sh * zh;
    float tail = fmaf(p, C, 2.0f * sl);
    tail = fmaf(sh * zl, 0.66666666667f, tail);
    float lh = 2.0f * sh;
    float fe = (float)e;
    float A  = fe * 0.69314575195f;
    float rh = A + lh;
    float rl = lh - (rh - A);
    float small = fmaf(fe, 1.4286067653e-06f, tail) + rl;
    return rh + small;
}

__device__ __forceinline__ float gumbel_from_bits(unsigned bits) {
    float U  = __uint_as_float((bits >> 9) | 0x3f800000u) - 1.0f;
    float t1 = U + 1e-10f;
    float L1 = log_df(t1);
    float t2 = (0.0f - L1) + 1e-10f;
    float L2 = log_df(t2);
    return 0.0f - L2;
}

// ---------------- fused prep: node transform + gumbel noise ----------------
// blocks [0,1024): node rows (2 per block).  blocks [1024,5120): gumbel.
__global__ __launch_bounds__(256) void prep_kernel(const float* __restrict__ feats,
                                                   const float* __restrict__ Wout,
                                                   const float* __restrict__ bout) {
    int b = blockIdx.x;
    if (b < 1024) {
        __shared__ float f[2][Dd];
        int half = threadIdx.x >> 7;
        int t    = threadIdx.x & 127;
        int row  = b * 2 + half;
        if (t < Dd) f[half][t] = feats[row * Dd + t];
        __syncthreads();
        int col  = t & 63;
        bool isA = (t < 64);
        const float* W = Wout + (isA ? 0 : Dd * Dd);
        float acc = isA ? bout[col] : 0.0f;
#pragma unroll
        for (int k = 0; k < Dd; k++) acc = fmaf(f[half][k], W[k * Dd + col], acc);
        if (isA) g_A[row * Dd + col] = acc;
        else     g_B[row * Dd + col] = acc;
    } else {
        int j = (b - 1024) * 256 + threadIdx.x;
        unsigned i0 = 2u * (unsigned)j;
        g_g0[j] = gumbel_from_bits(random_bits_at(i0));
        g_g1[j] = gumbel_from_bits(random_bits_at(i0 + 1u));
    }
}

// ---------------- edge kernel: 64 snd x 32 rec tile, 4x4 edges/thread -------
// grid (8,16,4) = 512 blocks, 128 threads.
__global__ __launch_bounds__(128) void edge_kernel(const float* __restrict__ Wcat,
                                                   const float* __restrict__ bcat,
                                                   float* __restrict__ out) {
    int st = blockIdx.x, rt = blockIdx.y, head = blockIdx.z;
    __shared__ float As[64][68];    // [k][snd], row stride 272B (16B-aligned float4 reads)
    __shared__ float Bs[64][36];    // [k][rec], row stride 144B
    __shared__ float wc0[64], wc1[64];
    __shared__ unsigned hist[2048];
    int t = threadIdx.x;
    for (int i = t; i < 2048; i += 128) hist[i] = 0u;
    if (t < 64) { wc0[t] = Wcat[t * 2]; wc1[t] = Wcat[t * 2 + 1]; }

    // load slabs: A 64 nodes x 64k (1024 float4), B 32 nodes x 64k (512 float4)
    const float4* A4 = (const float4*)(g_A + (head * Nn + st * 64) * Dd);
    const float4* B4 = (const float4*)(g_B + (head * Nn + rt * 32) * Dd);
#pragma unroll
    for (int q = 0; q < 8; q++) {
        int i4 = q * 128 + t;
        int s  = i4 >> 4;
        int kb = (i4 & 15) * 4;
        float4 v = A4[i4];
        As[kb + 0][s] = v.x; As[kb + 1][s] = v.y; As[kb + 2][s] = v.z; As[kb + 3][s] = v.w;
    }
#pragma unroll
    for (int q = 0; q < 4; q++) {
        int i4 = q * 128 + t;
        int s  = i4 >> 4;
        int kb = (i4 & 15) * 4;
        float4 v = B4[i4];
        Bs[kb + 0][s] = v.x; Bs[kb + 1][s] = v.y; Bs[kb + 2][s] = v.z; Bs[kb + 3][s] = v.w;
    }
    __syncthreads();

    int tx = t & 15, ty = t >> 4;          // snd group tx*4, rec group ty*4
    float acc0[4][4], acc1[4][4];
#pragma unroll
    for (int i = 0; i < 4; i++)
#pragma unroll
        for (int j = 0; j < 4; j++) { acc0[i][j] = 0.f; acc1[i][j] = 0.f; }

#pragma unroll 4
    for (int k = 0; k < 64; k++) {
        float4 a = *(const float4*)&As[k][tx * 4];
        float4 b = *(const float4*)&Bs[k][ty * 4];
        float w0 = wc0[k], w1 = wc1[k];
        float av[4] = {a.x, a.y, a.z, a.w};
        float bv[4] = {b.x, b.y, b.z, b.w};
#pragma unroll
        for (int i = 0; i < 4; i++)
#pragma unroll
            for (int j = 0; j < 4; j++) {
                float hr = fmaxf(av[j] + bv[i], 0.0f);
                acc0[i][j] = fmaf(hr, w0, acc0[i][j]);
                acc1[i][j] = fmaf(hr, w1, acc1[i][j]);
            }
    }

    float bc0 = bcat[0], bc1 = bcat[1];
    int rec0 = rt * 32 + ty * 4;
    int snd0 = st * 64 + tx * 4;
#pragma unroll
    for (int i = 0; i < 4; i++) {
        int gidx = head * Ee + (rec0 + i) * Nn + snd0;   // snd0 multiple of 4 -> 16B aligned
        float4 G0 = *reinterpret_cast<const float4*>(g_g0 + gidx);
        float4 G1 = *reinterpret_cast<const float4*>(g_g1 + gidx);
        float g0a[4] = {G0.x, G0.y, G0.z, G0.w};
        float g1a[4] = {G1.x, G1.y, G1.z, G1.w};
        float cma[4], pa[4];
#pragma unroll
        for (int j = 0; j < 4; j++) {
            float l0 = acc0[i][j] + bc0;
            float l1 = acc1[i][j] + bc1;
            float m  = fmaxf(l0, l1);
            float e0v = expf(l0 - m);
            float e1v = expf(l1 - m);
            float p = e1v / (e0v + e1v);
            pa[j] = p;
            float s0 = l0 + g0a[j];
            float s1 = l1 + g1a[j];
            cma[j] = (s1 > s0) ? 1.0f : 0.0f;
            atomicAdd(&hist[__float_as_uint(p) >> 21], 1u);
        }
        float4 cmv; cmv.x = cma[0]; cmv.y = cma[1]; cmv.z = cma[2]; cmv.w = cma[3];
        float4 pv;  pv.x  = pa[0];  pv.y  = pa[1];  pv.z  = pa[2];  pv.w  = pa[3];
        float4 zv;  zv.x = 0.f; zv.y = 0.f; zv.z = 0.f; zv.w = 0.f;
        *reinterpret_cast<float4*>(out + gidx)          = cmv;
        *reinterpret_cast<float4*>(out + HE + gidx)     = pv;
        *reinterpret_cast<float4*>(out + 2 * HE + gidx) = zv;
    }
    __syncthreads();
    for (int i = t; i < 2048; i += 128)
        if (hist[i]) atomicAdd(&g_hist[head][i], hist[i]);
}

// ---------------- suffix-scan threshold -----------
__device__ __forceinline__ void threshold_scan(const unsigned* hist, int target,
                                               int* bstar_out, int* cabove_out) {
    int t = threadIdx.x;
    __shared__ int psum[256];
    int local[8];
    int base = t * 8;
    int ls = 0;
#pragma unroll
    for (int i = 0; i < 8; i++) { local[i] = (int)hist[base + i]; ls += local[i]; }
    psum[t] = ls;
    __syncthreads();
    for (int off = 1; off < 256; off <<= 1) {
        int add = (t + off < 256) ? psum[t + off] : 0;
        __syncthreads();
        psum[t] += add;
        __syncthreads();
    }
    int cum = psum[t] - ls;
#pragma unroll
    for (int i = 7; i >= 0; i--) {
        if (cum < target && cum + local[i] >= target) {
            *bstar_out = base + i;
            *cabove_out = cum;
        }
        cum += local[i];
    }
    __syncthreads();
}

__global__ __launch_bounds__(256) void threshold1_kernel() {
    int h = blockIdx.x;
    threshold_scan(g_hist[h], Kk, &g_bstar[h], &g_cabove[h]);
    int base = threadIdx.x * 8;
#pragma unroll
    for (int i = 0; i < 8; i++) g_hist[h][base + i] = 0u;
}

// Mark bins > b1*; compact bin == b1* into g_cand + build level-2 histogram.
// 8 elements per thread (2 independent float4 loads), grid 512.
__global__ __launch_bounds__(256) void collect1_kernel(float* __restrict__ out) {
    int base = (blockIdx.x * 256 + threadIdx.x) * 8;
    int h = base >> 18;
    int bs = g_bstar[h];
    float4 p0 = *reinterpret_cast<const float4*>(out + HE + base);
    float4 p1 = *reinterpret_cast<const float4*>(out + HE + base + 4);
    float pv[8] = {p0.x, p0.y, p0.z, p0.w, p1.x, p1.y, p1.z, p1.w};
#pragma unroll
    for (int q = 0; q < 8; q++) {
        unsigned bits = __float_as_uint(pv[q]);
        int bin = (int)(bits >> 21);
        if (bin >= bs) {
            int idx = base + q;
            if (bin > bs) {
                out[2 * HE + idx] = 1.0f;
            } else {
                unsigned e = (unsigned)(idx & (Ee - 1));
                atomicAdd(&g_hist2[h][(bits >> 10) & 2047], 1u);
                int p = atomicAdd(&g_candn[h], 1);
                if (p < CAND_MAX)
                    g_cand[h][p] = (((unsigned long long)bits) << 32)
                                 | (unsigned long long)((unsigned)(Ee - 1) - e);
            }
        }
    }
}

// Per head: threshold2 + mark/collect from compacted list + iterative topk
__global__ __launch_bounds__(256) void final_kernel(float* __restrict__ out) {
    int h = blockIdx.x, t = threadIdx.x;
    __shared__ int sb2, sc2;
    threshold_scan(g_hist2[h], Kk - g_cabove[h], &sb2, &sc2);
    {
        int base = t * 8;
#pragma unroll
        for (int i = 0; i < 8; i++) g_hist2[h][base + i] = 0u;
    }
    __syncthreads();
    int b2 = sb2, c2 = sc2;

    __shared__ unsigned long long lv[1024];
    __shared__ int lc;
    if (t == 0) lc = 0;
    __syncthreads();
    int n = g_candn[h]; if (n > CAND_MAX) n = CAND_MAX;
    for (int i = t; i < n; i += 256) {
        unsigned long long v = g_cand[h][i];
        unsigned bits = (unsigned)(v >> 32);
        int bin2 = (int)((bits >> 10) & 2047);
        if (bin2 > b2) {
            unsigned e = (unsigned)(Ee - 1) - (unsigned)(v & 0xffffffffull);
            out[2 * HE + h * Ee + (int)e] = 1.0f;
        } else if (bin2 == b2) {
            int p = atomicAdd(&lc, 1);
            if (p < 1024) lv[p] = v;
        }
    }
    __syncthreads();
    int take = Kk - g_cabove[h] - c2;
    int m = lc; if (m > 1024) m = 1024;
    __shared__ unsigned long long wmax[8];
    for (int it = 0; it < take; it++) {
        unsigned long long best = 0ull;
        for (int i = t; i < m; i += 256) { unsigned long long v = lv[i]; if (v > best) best = v; }
#pragma unroll
        for (int o = 16; o > 0; o >>= 1) {
            unsigned long long v = __shfl_xor_sync(0xffffffffu, best, o);
            if (v > best) best = v;
        }
        if ((t & 31) == 0) wmax[t >> 5] = best;
        __syncthreads();
        if (t == 0) {
            unsigned long long w = wmax[0];
#pragma unroll
            for (int i = 1; i < 8; i++) if (wmax[i] > w) w = wmax[i];
            wmax[0] = w;
        }
        __syncthreads();
        unsigned long long win = wmax[0];
        for (int i = t; i < m; i += 256) if (lv[i] == win) lv[i] = 0ull;
        if (t == 0) {
            unsigned e = (unsigned)(Ee - 1) - (unsigned)(win & 0xffffffffull);
            out[2 * HE + h * Ee + (int)e] = 1.0f;
        }
        __syncthreads();
    }
    if (t == 0) g_candn[h] = 0;
}

// ---------------- launch ----------------
extern "C" void kernel_launch(void* const* d_in, const int* in_sizes, int n_in,
                              void* d_out, int out_size) {
    const float* feats = (const float*)d_in[0];
    const float* W_out = (const float*)d_in[1];
    const float* b_out = (const float*)d_in[2];
    const float* W_cat = (const float*)d_in[3];
    const float* b_cat = (const float*)d_in[4];
    float* out = (float*)d_out;

    prep_kernel<<<1024 + HE / 256, 256>>>(feats, W_out, b_out);
    {
        dim3 grid(Nn / 64, Nn / 32, Hh);
        edge_kernel<<<grid, 128>>>(W_cat, b_cat, out);
    }
    threshold1_kernel<<<Hh, 256>>>();
    collect1_kernel<<<HE / 2048, 256>>>(out);
    final_kernel<<<Hh, 256>>>(out);
}